// round 16
// baseline (speedup 1.0000x reference)
#include <cuda_runtime.h>
#include <cuda_fp16.h>
#include <math.h>
#include <stdint.h>

#define BB   2
#define SS   2048
#define HH   2048
#define NHQ  32
#define NHKV 8
#define DK   64
#define DV   64
#define QKV_OUT 3072
#define ATTN_SCALE 0.125f
#define MM   (BB * SS)  // 4096

// ---------------------------------------------------------------------------
// Scratch (device globals)
// ---------------------------------------------------------------------------
__device__ float  g_qkv [BB * SS * QKV_OUT];        // fp32 QKV (V section only)
__device__ __half g_ah[MM * HH];                    // A hi (x, then attn-out)
__device__ __half g_al[MM * HH];                    // A lo
__device__ __half g_wqh[QKV_OUT * HH];              // Wqkv^T hi [N,K]
__device__ __half g_woh[HH * HH];                   // Wout^T hi [N,K]
// attention operands (fp16)
__device__ __half g_qh [BB * NHQ  * SS * DK];       // scaled Q hi
__device__ __half g_ql [BB * NHQ  * SS * DK];       // scaled Q lo
__device__ __half g_kh [BB * NHKV * SS * DK];       // K hi
__device__ __half g_vth[BB * NHKV * DV * SS];       // V^T hi [b][n][d][s]

// ---------------------------------------------------------------------------
// Helpers
// ---------------------------------------------------------------------------
__device__ __forceinline__ uint32_t smem_to_u32(const void* p) {
    uint32_t a;
    asm("{ .reg .u64 t; cvta.to.shared.u64 t, %1; cvt.u32.u64 %0, t; }" : "=r"(a) : "l"(p));
    return a;
}
__device__ __forceinline__ void cp_async16(uint32_t dst, const void* src) {
    asm volatile("cp.async.cg.shared.global [%0], [%1], 16;" :: "r"(dst), "l"(src));
}
#define CP_COMMIT()  asm volatile("cp.async.commit_group;")
#define CP_WAIT2()   asm volatile("cp.async.wait_group 2;")
#define CP_WAIT1()   asm volatile("cp.async.wait_group 1;")
#define CP_WAIT0()   asm volatile("cp.async.wait_group 0;")

#define LDMX4(r, addr) \
    asm volatile("ldmatrix.sync.aligned.m8n8.x4.shared.b16 {%0,%1,%2,%3}, [%4];" \
        : "=r"((r)[0]), "=r"((r)[1]), "=r"((r)[2]), "=r"((r)[3]) : "r"(addr))

__device__ __forceinline__ void mma16816(float* d, const uint32_t* a, uint32_t b0, uint32_t b1)
{
    asm volatile(
        "mma.sync.aligned.m16n8k16.row.col.f32.f16.f16.f32 "
        "{%0,%1,%2,%3}, {%4,%5,%6,%7}, {%8,%9}, {%0,%1,%2,%3};"
        : "+f"(d[0]), "+f"(d[1]), "+f"(d[2]), "+f"(d[3])
        : "r"(a[0]), "r"(a[1]), "r"(a[2]), "r"(a[3]), "r"(b0), "r"(b1));
}

// fp32 pair -> packed fp16 hi + packed fp16 lo (residual)
__device__ __forceinline__ void split_pack(float a, float b, uint32_t& hi, uint32_t& lo)
{
    __half ha = __float2half_rn(a), hb = __float2half_rn(b);
    __half la = __float2half_rn(a - __half2float(ha));
    __half lb = __float2half_rn(b - __half2float(hb));
    hi = ((uint32_t)__half_as_ushort(hb) << 16) | __half_as_ushort(ha);
    lo = ((uint32_t)__half_as_ushort(lb) << 16) | __half_as_ushort(la);
}
__device__ __forceinline__ uint32_t pack_h2(float a, float b)
{
    return ((uint32_t)__half_as_ushort(__float2half_rn(b)) << 16)
         | __half_as_ushort(__float2half_rn(a));
}

// ---------------------------------------------------------------------------
// Prep kernels
// ---------------------------------------------------------------------------
__global__ __launch_bounds__(256)
void split_f32(const float* __restrict__ in, __half* __restrict__ hi,
               __half* __restrict__ lo, int n)
{
    int i = (blockIdx.x * blockDim.x + threadIdx.x) * 4;
    if (i >= n) return;
    float4 v = *reinterpret_cast<const float4*>(in + i);
    uint32_t h0, l0, h1, l1;
    split_pack(v.x, v.y, h0, l0);
    split_pack(v.z, v.w, h1, l1);
    reinterpret_cast<uint32_t*>(hi + i)[0] = h0;
    reinterpret_cast<uint32_t*>(hi + i)[1] = h1;
    reinterpret_cast<uint32_t*>(lo + i)[0] = l0;
    reinterpret_cast<uint32_t*>(lo + i)[1] = l1;
}

__global__ __launch_bounds__(256)
void transpose_h(const float* __restrict__ W, __half* __restrict__ Th, int K, int N)
{
    __shared__ float tile[32][33];
    const int n0 = blockIdx.x * 32;
    const int k0 = blockIdx.y * 32;
    const int tx = threadIdx.x;
    const int ty = threadIdx.y;
    #pragma unroll
    for (int r = ty; r < 32; r += 8)
        tile[r][tx] = W[(size_t)(k0 + r) * N + n0 + tx];
    __syncthreads();
    #pragma unroll
    for (int r = ty; r < 32; r += 8)
        Th[(size_t)(n0 + r) * K + k0 + tx] = __float2half_rn(tile[tx][r]);
}

// V section of g_qkv -> transposed [b][n][d][s] fp16 hi only
__global__ __launch_bounds__(256)
void transpose_v()
{
    __shared__ float tile[32][33];
    const int s0 = blockIdx.x * 32;
    const int d0 = blockIdx.y * 32;
    const int bz = blockIdx.z;
    const int b  = bz >> 3, n = bz & 7;
    const int tx = threadIdx.x;
    const int ty = threadIdx.y;
    const int colbase = 2560 + n * 64 + d0;
    #pragma unroll
    for (int r = ty; r < 32; r += 8)
        tile[r][tx] = g_qkv[(size_t)(b * SS + s0 + r) * QKV_OUT + colbase + tx];
    __syncthreads();
    #pragma unroll
    for (int r = ty; r < 32; r += 8) {
        size_t o = ((size_t)(b * NHKV + n) * DV + d0 + r) * SS + s0 + tx;
        g_vth[o] = __float2half_rn(tile[tx][r]);
    }
}

// ---------------------------------------------------------------------------
// HMMA fp16 2-product GEMM, 3-stage cp.async pipeline, ldmatrix frags.
// CTA 128x128, K-chunk 32, 4 warps (64x64 warp tiles), 2 CTAs/SM.
// mode 0: fused QKV epilogue (Q->g_qh/g_ql scaled, K->g_kh, V->g_qkv fp32)
// mode 1: C = result + bias (fp32, for output projection)
// ---------------------------------------------------------------------------
#define SPAD 40
#define TILE_ELEMS (128 * SPAD)
#define TILE_BYTES (TILE_ELEMS * 2)       // 10240
#define NSTAGE 3
#define GSMEM_BYTES (TILE_BYTES * 3 * NSTAGE)   // 92160

__global__ __launch_bounds__(128, 2)
void gemm_hmma(const __half* __restrict__ Ah, const __half* __restrict__ Al,
               const __half* __restrict__ Bh,
               float* __restrict__ C, const float* __restrict__ bias,
               int M, int N, int K, int mode)
{
    extern __shared__ __half dsm[];
    const int tid  = threadIdx.x;
    const int wid  = tid >> 5;
    const int lane = tid & 31;
    const int wm   = (wid >> 1) * 64;
    const int wn   = (wid & 1) * 64;
    const int bm   = blockIdx.y * 128;
    const int bn   = blockIdx.x * 128;
    const int lrow = lane >> 2;
    const int lkb  = (lane & 3) * 2;
    const uint32_t sb = smem_to_u32(dsm);

    const int arow_pat = (lane & 7) + ((lane >> 3) & 1) * 8;
    const int acol_pat = (lane >> 4) * 8;
    const int brow_pat = (lane & 7) + (lane >> 4) * 8;
    const int bcol_pat = ((lane >> 3) & 1) * 8;

    float acc[4][8][4];
    #pragma unroll
    for (int i = 0; i < 4; i++)
        #pragma unroll
        for (int j = 0; j < 8; j++)
            #pragma unroll
            for (int c = 0; c < 4; c++) acc[i][j][c] = 0.0f;

    const int nCh = K >> 5;

    auto issue = [&](int k0, int st) {
        #pragma unroll
        for (int i = 0; i < 4; i++) {
            const int idx = tid + i * 128;
            const int r   = idx >> 2;
            const int c8  = (idx & 3) * 8;
            const size_t gA = (size_t)(bm + r) * K + k0 + c8;
            const size_t gB = (size_t)(bn + r) * K + k0 + c8;
            const uint32_t so = (uint32_t)((r * SPAD + c8) * 2);
            cp_async16(sb + (0 * NSTAGE + st) * TILE_BYTES + so, Ah + gA);
            cp_async16(sb + (1 * NSTAGE + st) * TILE_BYTES + so, Al + gA);
            cp_async16(sb + (2 * NSTAGE + st) * TILE_BYTES + so, Bh + gB);
        }
        CP_COMMIT();
    };

    issue(0, 0);
    issue(32, 1);
    for (int c = 0; c < nCh; c++) {
        if (c + 2 < nCh)      { issue((c + 2) << 5, (c + 2) % NSTAGE); CP_WAIT2(); }
        else if (c + 1 < nCh) { CP_WAIT1(); }
        else                  { CP_WAIT0(); }
        __syncthreads();

        const int st = c % NSTAGE;
        const uint32_t aAh = sb + (0 * NSTAGE + st) * TILE_BYTES;
        const uint32_t aAl = sb + (1 * NSTAGE + st) * TILE_BYTES;
        const uint32_t aBh = sb + (2 * NSTAGE + st) * TILE_BYTES;

        #pragma unroll
        for (int ks = 0; ks < 2; ks++) {
            uint32_t ah[4][4], al[4][4];
            #pragma unroll
            for (int mi = 0; mi < 4; mi++) {
                const uint32_t ra = (uint32_t)(((wm + mi * 16 + arow_pat) * SPAD
                                               + ks * 16 + acol_pat) * 2);
                LDMX4(ah[mi], aAh + ra);
                LDMX4(al[mi], aAl + ra);
            }
            #pragma unroll
            for (int p = 0; p < 4; p++) {
                uint32_t br[4];
                const uint32_t rb = (uint32_t)(((wn + p * 16 + brow_pat) * SPAD
                                               + ks * 16 + bcol_pat) * 2);
                LDMX4(br, aBh + rb);
                #pragma unroll
                for (int mi = 0; mi < 4; mi++) {
                    mma16816(acc[mi][2 * p],     ah[mi], br[0], br[1]);
                    mma16816(acc[mi][2 * p],     al[mi], br[0], br[1]);
                    mma16816(acc[mi][2 * p + 1], ah[mi], br[2], br[3]);
                    mma16816(acc[mi][2 * p + 1], al[mi], br[2], br[3]);
                }
            }
        }
        __syncthreads();
    }

    if (mode == 1) {
        #pragma unroll
        for (int mi = 0; mi < 4; mi++) {
            const int r0 = bm + wm + mi * 16 + lrow;
            #pragma unroll
            for (int ni = 0; ni < 8; ni++) {
                const int col = bn + wn + ni * 8 + lkb;
                const float b0 = bias[col], b1 = bias[col + 1];
                float2 v0 = make_float2(acc[mi][ni][0] + b0, acc[mi][ni][1] + b1);
                float2 v1 = make_float2(acc[mi][ni][2] + b0, acc[mi][ni][3] + b1);
                *reinterpret_cast<float2*>(&C[(size_t)r0 * N + col])       = v0;
                *reinterpret_cast<float2*>(&C[(size_t)(r0 + 8) * N + col]) = v1;
            }
        }
    } else {
        // Fused QKV epilogue
        #pragma unroll
        for (int mi = 0; mi < 4; mi++) {
            const int r0 = bm + wm + mi * 16 + lrow;
            #pragma unroll
            for (int ni = 0; ni < 8; ni++) {
                const int col = bn + wn + ni * 8 + lkb;
                #pragma unroll
                for (int h = 0; h < 2; h++) {
                    const int rr = r0 + h * 8;
                    const float a0 = acc[mi][ni][2 * h + 0];
                    const float a1 = acc[mi][ni][2 * h + 1];
                    const int bb = rr >> 11, s = rr & 2047;
                    if (col < 2048) {
                        uint32_t hi, lo;
                        split_pack(a0 * ATTN_SCALE, a1 * ATTN_SCALE, hi, lo);
                        size_t o = ((size_t)(bb * NHQ + (col >> 6)) * SS + s) * DK + (col & 63);
                        *reinterpret_cast<uint32_t*>(g_qh + o) = hi;
                        *reinterpret_cast<uint32_t*>(g_ql + o) = lo;
                    } else if (col < 2560) {
                        const int cc = col - 2048;
                        size_t o = ((size_t)(bb * NHKV + (cc >> 6)) * SS + s) * DK + (cc & 63);
                        *reinterpret_cast<uint32_t*>(g_kh + o) = pack_h2(a0, a1);
                    } else {
                        *reinterpret_cast<float2*>(&g_qkv[(size_t)rr * QKV_OUT + col]) =
                            make_float2(a0, a1);
                    }
                }
            }
        }
    }
}

// ---------------------------------------------------------------------------
// Tensor-core causal flash attention (GQA), fp16 2-product + ldmatrix.
// ---------------------------------------------------------------------------
#define APAD 72

__global__ __launch_bounds__(128)
void attn_tc()
{
    __shared__ __half sKh[64][APAD];
    __shared__ __half sVh[64][APAD];

    const int tid  = threadIdx.x;
    const int wid  = tid >> 5;
    const int lane = tid & 31;
    const int g    = lane >> 2;
    const int tig  = lane & 3;
    const int qt   = (int)gridDim.x - 1 - (int)blockIdx.x;
    const int bh   = blockIdx.y;
    const int b    = bh >> 5;
    const int hq   = bh & 31;
    const int n    = hq >> 2;
    const int wm   = wid * 16;

    const uint32_t sK = smem_to_u32(&sKh[0][0]);
    const uint32_t sV = smem_to_u32(&sVh[0][0]);
    const int arow_pat = (lane & 7) + ((lane >> 3) & 1) * 8;
    const int acol_pat = (lane >> 4) * 8;
    const int brow_pat = (lane & 7) + (lane >> 4) * 8;
    const int bcol_pat = ((lane >> 3) & 1) * 8;

    const __half* qhb = g_qh + ((size_t)(b * NHQ + hq) * SS + qt * 64) * DK;
    const __half* qlb = g_ql + ((size_t)(b * NHQ + hq) * SS + qt * 64) * DK;
    #pragma unroll
    for (int it = 0; it < 4; it++) {
        const int idx = it * 128 + tid;
        const int r = idx >> 3, c8 = (idx & 7) * 8;
        *reinterpret_cast<uint4*>(&sKh[r][c8]) = *reinterpret_cast<const uint4*>(qhb + r * DK + c8);
        *reinterpret_cast<uint4*>(&sVh[r][c8]) = *reinterpret_cast<const uint4*>(qlb + r * DK + c8);
    }
    __syncthreads();
    uint32_t qh[4][4], ql[4][4];
    #pragma unroll
    for (int ks = 0; ks < 4; ks++) {
        const uint32_t ra = (uint32_t)(((wm + arow_pat) * APAD + ks * 16 + acol_pat) * 2);
        LDMX4(qh[ks], sK + ra);
        LDMX4(ql[ks], sV + ra);
    }

    float oacc[8][4];
    #pragma unroll
    for (int i = 0; i < 8; i++)
        #pragma unroll
        for (int c = 0; c < 4; c++) oacc[i][c] = 0.0f;
    float m0 = -INFINITY, m1 = -INFINITY, l0 = 0.0f, l1 = 0.0f;

    const __half* khb = g_kh  + (size_t)(b * NHKV + n) * SS * DK;
    const __half* vhb = g_vth + (size_t)(b * NHKV + n) * DV * SS;

    for (int kt = 0; kt <= qt; kt++) {
        __syncthreads();
        #pragma unroll
        for (int it = 0; it < 4; it++) {
            const int idx = it * 128 + tid;
            const int r = idx >> 3, c8 = (idx & 7) * 8;
            *reinterpret_cast<uint4*>(&sKh[r][c8]) =
                *reinterpret_cast<const uint4*>(khb + (size_t)(kt * 64 + r) * DK + c8);
            *reinterpret_cast<uint4*>(&sVh[r][c8]) =
                *reinterpret_cast<const uint4*>(vhb + (size_t)r * SS + kt * 64 + c8);
        }
        __syncthreads();

        float sacc[8][4];
        #pragma unroll
        for (int i = 0; i < 8; i++)
            #pragma unroll
            for (int c = 0; c < 4; c++) sacc[i][c] = 0.0f;

        #pragma unroll
        for (int p = 0; p < 4; p++) {
            #pragma unroll
            for (int ks = 0; ks < 4; ks++) {
                uint32_t kr[4];
                const uint32_t rb = (uint32_t)(((p * 16 + brow_pat) * APAD
                                               + ks * 16 + bcol_pat) * 2);
                LDMX4(kr, sK + rb);
                mma16816(sacc[2 * p],     qh[ks], kr[0], kr[1]);
                mma16816(sacc[2 * p],     ql[ks], kr[0], kr[1]);
                mma16816(sacc[2 * p + 1], qh[ks], kr[2], kr[3]);
                mma16816(sacc[2 * p + 1], ql[ks], kr[2], kr[3]);
            }
        }

        if (kt == qt) {
            #pragma unroll
            for (int ni = 0; ni < 8; ni++) {
                #pragma unroll
                for (int c = 0; c < 4; c++) {
                    const int jl = ni * 8 + tig * 2 + (c & 1);
                    const int il = wm + g + ((c & 2) ? 8 : 0);
                    if (jl > il) sacc[ni][c] = -INFINITY;
                }
            }
        }

        float rmax0 = -INFINITY, rmax1 = -INFINITY;
        #pragma unroll
        for (int ni = 0; ni < 8; ni++) {
            rmax0 = fmaxf(rmax0, fmaxf(sacc[ni][0], sacc[ni][1]));
            rmax1 = fmaxf(rmax1, fmaxf(sacc[ni][2], sacc[ni][3]));
        }
        rmax0 = fmaxf(rmax0, __shfl_xor_sync(0xffffffffu, rmax0, 1));
        rmax0 = fmaxf(rmax0, __shfl_xor_sync(0xffffffffu, rmax0, 2));
        rmax1 = fmaxf(rmax1, __shfl_xor_sync(0xffffffffu, rmax1, 1));
        rmax1 = fmaxf(rmax1, __shfl_xor_sync(0xffffffffu, rmax1, 2));

        const float mn0 = fmaxf(m0, rmax0);
        const float mn1 = fmaxf(m1, rmax1);
        const float cr0 = __expf(m0 - mn0);
        const float cr1 = __expf(m1 - mn1);
        float rs0 = 0.0f, rs1 = 0.0f;
        #pragma unroll
        for (int ni = 0; ni < 8; ni++) {
            float p0 = __expf(sacc[ni][0] - mn0);
            float p1 = __expf(sacc[ni][1] - mn0);
            float p2 = __expf(sacc[ni][2] - mn1);
            float p3 = __expf(sacc[ni][3] - mn1);
            sacc[ni][0] = p0; sacc[ni][1] = p1; sacc[ni][2] = p2; sacc[ni][3] = p3;
            rs0 += p0 + p1;
            rs1 += p2 + p3;
        }
        rs0 += __shfl_xor_sync(0xffffffffu, rs0, 1);
        rs0 += __shfl_xor_sync(0xffffffffu, rs0, 2);
        rs1 += __shfl_xor_sync(0xffffffffu, rs1, 1);
        rs1 += __shfl_xor_sync(0xffffffffu, rs1, 2);
        l0 = l0 * cr0 + rs0;
        l1 = l1 * cr1 + rs1;
        m0 = mn0; m1 = mn1;
        #pragma unroll
        for (int ni = 0; ni < 8; ni++) {
            oacc[ni][0] *= cr0; oacc[ni][1] *= cr0;
            oacc[ni][2] *= cr1; oacc[ni][3] *= cr1;
        }

        #pragma unroll
        for (int ks = 0; ks < 4; ks++) {
            uint32_t ph[4], pl[4];
            split_pack(sacc[2 * ks][0],     sacc[2 * ks][1],     ph[0], pl[0]);
            split_pack(sacc[2 * ks][2],     sacc[2 * ks][3],     ph[1], pl[1]);
            split_pack(sacc[2 * ks + 1][0], sacc[2 * ks + 1][1], ph[2], pl[2]);
            split_pack(sacc[2 * ks + 1][2], sacc[2 * ks + 1][3], ph[3], pl[3]);
            #pragma unroll
            for (int p = 0; p < 4; p++) {
                uint32_t vr[4];
                const uint32_t rb = (uint32_t)(((p * 16 + brow_pat) * APAD
                                               + ks * 16 + bcol_pat) * 2);
                LDMX4(vr, sV + rb);
                mma16816(oacc[2 * p],     ph, vr[0], vr[1]);
                mma16816(oacc[2 * p],     pl, vr[0], vr[1]);
                mma16816(oacc[2 * p + 1], ph, vr[2], vr[3]);
                mma16816(oacc[2 * p + 1], pl, vr[2], vr[3]);
            }
        }
    }

    const float inv0 = 1.0f / l0;
    const float inv1 = 1.0f / l1;
    const size_t r0g = (size_t)(b * SS + qt * 64 + wm + g);
    const size_t r1g = r0g + 8;
    #pragma unroll
    for (int ni = 0; ni < 8; ni++) {
        const int col = hq * DV + ni * 8 + tig * 2;
        uint32_t hi, lo;
        split_pack(oacc[ni][0] * inv0, oacc[ni][1] * inv0, hi, lo);
        *reinterpret_cast<uint32_t*>(&g_ah[r0g * HH + col]) = hi;
        *reinterpret_cast<uint32_t*>(&g_al[r0g * HH + col]) = lo;
        split_pack(oacc[ni][2] * inv1, oacc[ni][3] * inv1, hi, lo);
        *reinterpret_cast<uint32_t*>(&g_ah[r1g * HH + col]) = hi;
        *reinterpret_cast<uint32_t*>(&g_al[r1g * HH + col]) = lo;
    }
}

// ---------------------------------------------------------------------------
// Launcher
// ---------------------------------------------------------------------------
extern "C" void kernel_launch(void* const* d_in, const int* in_sizes, int n_in,
                              void* d_out, int out_size)
{
    const float* x     = (const float*)d_in[0];
    const float* Wqkv  = (const float*)d_in[1];
    const float* Wout  = (const float*)d_in[2];
    const float* b_out = (const float*)d_in[3];
    float* out = (float*)d_out;

    float* qkv_p;
    __half *ah_p, *al_p, *wqh_p, *woh_p;
    cudaGetSymbolAddress((void**)&qkv_p, g_qkv);
    cudaGetSymbolAddress((void**)&ah_p,  g_ah);
    cudaGetSymbolAddress((void**)&al_p,  g_al);
    cudaGetSymbolAddress((void**)&wqh_p, g_wqh);
    cudaGetSymbolAddress((void**)&woh_p, g_woh);

    cudaFuncSetAttribute(gemm_hmma, cudaFuncAttributeMaxDynamicSharedMemorySize,
                         GSMEM_BYTES);

    // Prep: split x (hi/lo); transpose weights (hi only)
    {
        const int n = MM * HH;
        split_f32<<<n / (256 * 4), 256>>>(x, ah_p, al_p, n);
    }
    transpose_h<<<dim3(QKV_OUT / 32, HH / 32), dim3(32, 8)>>>(Wqkv, wqh_p, HH, QKV_OUT);
    transpose_h<<<dim3(HH / 32, HH / 32), dim3(32, 8)>>>(Wout, woh_p, HH, HH);

    // 1) QKV projection with fused Q/K split epilogue (V -> g_qkv fp32)
    gemm_hmma<<<dim3(QKV_OUT / 128, MM / 128), 128, GSMEM_BYTES>>>(
        ah_p, al_p, wqh_p, qkv_p, nullptr, MM, QKV_OUT, HH, 0);

    // 2) Transpose V (hi)
    transpose_v<<<dim3(SS / 32, DV / 32, BB * NHKV), dim3(32, 8)>>>();

    // 3) Tensor-core flash attention -> writes g_ah/g_al
    attn_tc<<<dim3(SS / 64, BB * NHQ), 128>>>();

    // 4) Output projection + bias
    gemm_hmma<<<dim3(HH / 128, MM / 128), 128, GSMEM_BYTES>>>(
        ah_p, al_p, woh_p, out, b_out, MM, HH, HH, 1);
}